// round 8
// baseline (speedup 1.0000x reference)
#include <cuda_runtime.h>

// Problem constants
#define D 256
#define EPS 1e-8f
#define TPB 256
#define MAIN_BLOCKS 1024

// Packed f32x2 helpers (sm_103a; ptxas never emits these from C++)
#define FMA2(d, a, b, c) \
    asm("fma.rn.f32x2 %0, %1, %2, %3;" : "=l"(d) : "l"(a), "l"(b), "l"(c))
#define MUL2(d, a, b) \
    asm("mul.rn.f32x2 %0, %1, %2;" : "=l"(d) : "l"(a), "l"(b))
#define PACK2(d, lo, hi) \
    asm("mov.b64 %0, {%1, %2};" : "=l"(d) : "f"(lo), "f"(hi))
#define UNPACK2(lo, hi, s) \
    asm("mov.b64 {%0, %1}, %2;" : "=f"(lo), "=f"(hi) : "l"(s))

// Precomputed per-node 1/max(||emb_row * w||, eps)
__device__ float g_inv[100000];

// ---------------------------------------------------------------------------
// Kernel 1: per-node inverse clamped norm. One warp per node, coalesced rows.
// ---------------------------------------------------------------------------
__global__ void norm_kernel(const float* __restrict__ emb,
                            const float* __restrict__ w, int nNodes) {
    int gw   = (blockIdx.x * blockDim.x + threadIdx.x) >> 5;
    int lane = threadIdx.x & 31;
    if (gw >= nNodes) return;

    const float4* row = (const float4*)(emb + (size_t)gw * D);
    const float4* wv  = (const float4*)w;
    float4 e0 = row[lane],      w0 = wv[lane];
    float4 e1 = row[lane + 32], w1 = wv[lane + 32];

    float t, acc = 0.f;
    t = e0.x * w0.x; acc = fmaf(t, t, acc);
    t = e0.y * w0.y; acc = fmaf(t, t, acc);
    t = e0.z * w0.z; acc = fmaf(t, t, acc);
    t = e0.w * w0.w; acc = fmaf(t, t, acc);
    t = e1.x * w1.x; acc = fmaf(t, t, acc);
    t = e1.y * w1.y; acc = fmaf(t, t, acc);
    t = e1.z * w1.z; acc = fmaf(t, t, acc);
    t = e1.w * w1.w; acc = fmaf(t, t, acc);

    #pragma unroll
    for (int off = 16; off; off >>= 1)
        acc += __shfl_xor_sync(0xffffffffu, acc, off);

    if (lane == 0) {
        float n = fmaxf(sqrtf(acc), EPS);
        g_inv[gw] = 1.0f / n;
    }
}

// ---------------------------------------------------------------------------
// Kernel 2: fused edge kernel (packed f32x2 math in both hot loops).
//   Phase 1: 8 lanes/edge, 4 edges concurrently/warp; packed MUL2/FMA2 dot.
//   Phase 2: thread-per-edge MLP; h2 as 16 packed accumulators.
// ---------------------------------------------------------------------------
__global__ void __launch_bounds__(TPB, 3)
edge_kernel(const int2* __restrict__ edge,
            const float* __restrict__ emb,
            const float* __restrict__ w,
            const float* __restrict__ W1,    // [64,2]
            const float* __restrict__ b1,    // [64]
            const float* __restrict__ W2,    // [32,64]
            const float* __restrict__ b2,    // [32]
            const float* __restrict__ Wp,    // [32]
            const float* __restrict__ bp,    // [1]
            float* __restrict__ out,
            int E, int totalWarps)
{
    __shared__ __align__(16) float2 s_w2p[128];      // weight_vec^2, packed pairs
    __shared__ float4 s_l1[64];                      // (W1[j][0], W1[j][1], b1[j], 0)
    __shared__ __align__(16) float2 s_W2P[64][16];   // W2^T packed: [j][i-pair]
    __shared__ __align__(16) float2 s_b2p[16];
    __shared__ float  s_Wp[32];
    __shared__ float  s_bp;
    __shared__ float  s_dot[TPB / 32][32];

    int tid = threadIdx.x;
    for (int i = tid; i < 128; i += TPB) {
        float a = w[2*i], b = w[2*i + 1];
        s_w2p[i] = make_float2(a * a, b * b);
    }
    for (int i = tid; i < 64; i += TPB)
        s_l1[i] = make_float4(W1[2*i], W1[2*i + 1], b1[i], 0.f);
    for (int i = tid; i < 1024; i += TPB) {
        int p = i & 15;        // output pair index (0..15)
        int c = i >> 4;        // hidden index j (0..63)
        s_W2P[c][p] = make_float2(W2[(2*p) * 64 + c], W2[(2*p + 1) * 64 + c]);
    }
    if (tid < 16) s_b2p[tid] = make_float2(b2[2*tid], b2[2*tid + 1]);
    if (tid < 32) s_Wp[tid] = Wp[tid];
    if (tid == 0) s_bp = bp[0];
    __syncthreads();

    int lane  = tid & 31;
    int wid   = tid >> 5;
    int g     = lane >> 3;         // edge-group 0..3
    int s     = lane & 7;          // sublane within group
    int gwarp = (blockIdx.x * TPB + tid) >> 5;

    const ulonglong2* w2v = (const ulonglong2*)s_w2p;

    for (long base = (long)gwarp * 32; base < E; base += (long)totalWarps * 32) {
        // Cooperative edge + inv-norm load: lane owns edge base+lane.
        int e  = (int)base + lane;
        int ce = e < E ? e : E - 1;
        int2 ep = edge[ce];
        float invp = g_inv[ep.x] * g_inv[ep.y];

        // ---- Phase 1: 8 iterations, 4 edges each, packed dot ----
        #pragma unroll
        for (int k = 0; k < 8; k++) {
            int src = k * 4 + g;
            int n0 = __shfl_sync(0xffffffffu, ep.x, src);
            int n1 = __shfl_sync(0xffffffffu, ep.y, src);

            const ulonglong2* r0 = (const ulonglong2*)(emb + (size_t)n0 * D);
            const ulonglong2* r1 = (const ulonglong2*)(emb + (size_t)n1 * D);

            unsigned long long pa = 0ull, pb = 0ull, pc = 0ull, pd = 0ull, m;
            #pragma unroll
            for (int t = 0; t < 8; t += 2) {
                ulonglong2 A0 = r0[s + 8*(t+0)], C0 = r1[s + 8*(t+0)], Q0 = w2v[s + 8*(t+0)];
                ulonglong2 A1 = r0[s + 8*(t+1)], C1 = r1[s + 8*(t+1)], Q1 = w2v[s + 8*(t+1)];
                MUL2(m, A0.x, C0.x); FMA2(pa, Q0.x, m, pa);
                MUL2(m, A0.y, C0.y); FMA2(pb, Q0.y, m, pb);
                MUL2(m, A1.x, C1.x); FMA2(pc, Q1.x, m, pc);
                MUL2(m, A1.y, C1.y); FMA2(pd, Q1.y, m, pd);
            }
            float l0, h0, l1, h1;
            UNPACK2(l0, h0, pa); UNPACK2(l1, h1, pb);
            float accA = (l0 + h0) + (l1 + h1);
            UNPACK2(l0, h0, pc); UNPACK2(l1, h1, pd);
            float acc = accA + (l0 + h0) + (l1 + h1);

            acc += __shfl_xor_sync(0xffffffffu, acc, 4);
            acc += __shfl_xor_sync(0xffffffffu, acc, 2);
            acc += __shfl_xor_sync(0xffffffffu, acc, 1);

            if (s == 0) s_dot[wid][k * 4 + g] = acc;
        }
        __syncwarp();

        float myDot = s_dot[wid][lane];
        float myCos = myDot * invp;

        // ---- Phase 2: thread-per-edge MLP, packed accumulators ----
        if (e < E) {
            unsigned long long h2p[16];
            const ulonglong2* b2v = (const ulonglong2*)s_b2p;
            #pragma unroll
            for (int i = 0; i < 8; i++) {
                ulonglong2 bb = b2v[i];
                h2p[2*i]     = bb.x;
                h2p[2*i + 1] = bb.y;
            }

            #pragma unroll 2
            for (int j = 0; j < 64; j++) {
                float4 c = s_l1[j];
                float hj = fmaxf(fmaf(myCos, c.x, fmaf(myDot, c.y, c.z)), 0.f);
                unsigned long long hj2;
                PACK2(hj2, hj, hj);
                const ulonglong2* colp = (const ulonglong2*)s_W2P[j];
                #pragma unroll
                for (int i = 0; i < 8; i++) {
                    ulonglong2 ww = colp[i];
                    FMA2(h2p[2*i],     ww.x, hj2, h2p[2*i]);
                    FMA2(h2p[2*i + 1], ww.y, hj2, h2p[2*i + 1]);
                }
            }

            float p = s_bp;
            #pragma unroll
            for (int i = 0; i < 16; i++) {
                float lo, hi;
                UNPACK2(lo, hi, h2p[i]);
                p = fmaf(s_Wp[2*i],     fmaxf(lo, 0.f), p);
                p = fmaf(s_Wp[2*i + 1], fmaxf(hi, 0.f), p);
            }

            out[e] = p;
        }
        __syncwarp();
    }
}

// ---------------------------------------------------------------------------
// Launch
// ---------------------------------------------------------------------------
extern "C" void kernel_launch(void* const* d_in, const int* in_sizes, int n_in,
                              void* d_out, int out_size) {
    const int2*  edge = (const int2*)d_in[0];     // int32 [E,2]
    const float* emb  = (const float*)d_in[1];    // [N,256]
    const float* wv   = (const float*)d_in[2];    // [1,256]
    const float* W1   = (const float*)d_in[3];    // [64,2]
    const float* b1   = (const float*)d_in[4];    // [64]
    const float* W2   = (const float*)d_in[5];    // [32,64]
    const float* b2   = (const float*)d_in[6];    // [32]
    const float* Wp   = (const float*)d_in[7];    // [1,32]
    const float* bp   = (const float*)d_in[8];    // [1]
    float* out = (float*)d_out;

    int E      = in_sizes[0] / 2;
    int nNodes = in_sizes[1] / D;

    int normBlocks = (nNodes * 32 + TPB - 1) / TPB;
    norm_kernel<<<normBlocks, TPB>>>(emb, wv, nNodes);

    int totalWarps = MAIN_BLOCKS * (TPB / 32);
    edge_kernel<<<MAIN_BLOCKS, TPB>>>(edge, emb, wv, W1, b1, W2, b2, Wp, bp,
                                      out, E, totalWarps);
}

// round 10
// speedup vs baseline: 1.1485x; 1.1485x over previous
#include <cuda_runtime.h>

// Problem constants
#define D 256
#define EPS 1e-8f
#define TPB 256
#define MAIN_BLOCKS 1024
#define N_NODES_MAX 100000

// Scratch: prescaled embeddings (emb * weight_vec) and per-node inverse norms.
__device__ float g_embs[(size_t)N_NODES_MAX * D];   // ~102 MB
__device__ float g_inv[N_NODES_MAX];

// ---------------------------------------------------------------------------
// Kernel 1: prescale rows by weight_vec AND compute inverse clamped norm.
// One warp per node; each lane handles 2 float4 chunks (8 floats).
// ---------------------------------------------------------------------------
__global__ void prescale_kernel(const float* __restrict__ emb,
                                const float* __restrict__ w, int nNodes) {
    int gw   = (blockIdx.x * blockDim.x + threadIdx.x) >> 5;
    int lane = threadIdx.x & 31;
    if (gw >= nNodes) return;

    const float4* row = (const float4*)(emb + (size_t)gw * D);
    float4*       dst = (float4*)(g_embs + (size_t)gw * D);
    const float4* wv  = (const float4*)w;

    float4 e0 = row[lane],      w0 = wv[lane];
    float4 e1 = row[lane + 32], w1 = wv[lane + 32];

    float4 x0 = make_float4(e0.x * w0.x, e0.y * w0.y, e0.z * w0.z, e0.w * w0.w);
    float4 x1 = make_float4(e1.x * w1.x, e1.y * w1.y, e1.z * w1.z, e1.w * w1.w);
    dst[lane]      = x0;
    dst[lane + 32] = x1;

    float acc = 0.f;
    acc = fmaf(x0.x, x0.x, acc);
    acc = fmaf(x0.y, x0.y, acc);
    acc = fmaf(x0.z, x0.z, acc);
    acc = fmaf(x0.w, x0.w, acc);
    acc = fmaf(x1.x, x1.x, acc);
    acc = fmaf(x1.y, x1.y, acc);
    acc = fmaf(x1.z, x1.z, acc);
    acc = fmaf(x1.w, x1.w, acc);

    #pragma unroll
    for (int off = 16; off; off >>= 1)
        acc += __shfl_xor_sync(0xffffffffu, acc, off);

    if (lane == 0) {
        float n = fmaxf(sqrtf(acc), EPS);
        g_inv[gw] = 1.0f / n;
    }
}

// ---------------------------------------------------------------------------
// Kernel 2: fused edge kernel (reads prescaled rows; pure FMA dot).
//   Phase 1: 8 lanes per edge, 4 edges concurrently per warp; dot = sum(a*c).
//   Phase 2: thread-per-edge MLP in two passes of 16 accumulators (reg diet).
// ---------------------------------------------------------------------------
__global__ void __launch_bounds__(TPB, 4)
edge_kernel(const int2* __restrict__ edge,
            const float* __restrict__ W1,    // [64,2]
            const float* __restrict__ b1,    // [64]
            const float* __restrict__ W2,    // [32,64]
            const float* __restrict__ b2,    // [32]
            const float* __restrict__ Wp,    // [32]
            const float* __restrict__ bp,    // [1]
            float* __restrict__ out,
            int E, int totalWarps)
{
    __shared__ float4 s_l1[64];           // (W1[j][0], W1[j][1], b1[j], 0)
    __shared__ float  s_W2T[64][32];      // W2 transposed: [j][i]
    __shared__ float  s_b2[32];
    __shared__ float  s_Wp[32];
    __shared__ float  s_bp;
    __shared__ float  s_dot[TPB / 32][32];

    int tid = threadIdx.x;
    for (int i = tid; i < 64; i += TPB)
        s_l1[i] = make_float4(W1[2*i], W1[2*i + 1], b1[i], 0.f);
    for (int i = tid; i < 2048; i += TPB) {
        int r = i & 31;        // output index i (0..31)
        int c = i >> 5;        // hidden index j (0..63)
        s_W2T[c][r] = W2[r * 64 + c];
    }
    if (tid < 32) { s_b2[tid] = b2[tid]; s_Wp[tid] = Wp[tid]; }
    if (tid == 0) s_bp = bp[0];
    __syncthreads();

    int lane  = tid & 31;
    int wid   = tid >> 5;
    int g     = lane >> 3;         // edge-group 0..3
    int s     = lane & 7;          // sublane within group
    int gwarp = (blockIdx.x * TPB + tid) >> 5;

    for (long base = (long)gwarp * 32; base < E; base += (long)totalWarps * 32) {
        // Cooperative edge + inv-norm load: lane owns edge base+lane.
        int e  = (int)base + lane;
        int ce = e < E ? e : E - 1;
        int2 ep = edge[ce];
        float invp = g_inv[ep.x] * g_inv[ep.y];

        // ---- Phase 1: 8 iterations, 4 edges each ----
        #pragma unroll
        for (int k = 0; k < 8; k++) {
            int src = k * 4 + g;
            int n0 = __shfl_sync(0xffffffffu, ep.x, src);
            int n1 = __shfl_sync(0xffffffffu, ep.y, src);

            const float4* r0 = (const float4*)(g_embs + (size_t)n0 * D);
            const float4* r1 = (const float4*)(g_embs + (size_t)n1 * D);

            float acc0 = 0.f, acc1 = 0.f, acc2 = 0.f, acc3 = 0.f;
            #pragma unroll
            for (int t = 0; t < 8; t += 4) {
                float4 a0 = r0[s + 8*(t+0)], c0 = r1[s + 8*(t+0)];
                float4 a1 = r0[s + 8*(t+1)], c1 = r1[s + 8*(t+1)];
                float4 a2 = r0[s + 8*(t+2)], c2 = r1[s + 8*(t+2)];
                float4 a3 = r0[s + 8*(t+3)], c3 = r1[s + 8*(t+3)];

                acc0 = fmaf(a0.x, c0.x, acc0);
                acc0 = fmaf(a0.y, c0.y, acc0);
                acc0 = fmaf(a0.z, c0.z, acc0);
                acc0 = fmaf(a0.w, c0.w, acc0);
                acc1 = fmaf(a1.x, c1.x, acc1);
                acc1 = fmaf(a1.y, c1.y, acc1);
                acc1 = fmaf(a1.z, c1.z, acc1);
                acc1 = fmaf(a1.w, c1.w, acc1);
                acc2 = fmaf(a2.x, c2.x, acc2);
                acc2 = fmaf(a2.y, c2.y, acc2);
                acc2 = fmaf(a2.z, c2.z, acc2);
                acc2 = fmaf(a2.w, c2.w, acc2);
                acc3 = fmaf(a3.x, c3.x, acc3);
                acc3 = fmaf(a3.y, c3.y, acc3);
                acc3 = fmaf(a3.z, c3.z, acc3);
                acc3 = fmaf(a3.w, c3.w, acc3);
            }
            float acc = (acc0 + acc1) + (acc2 + acc3);

            // reduce within 8-lane group (xor 4,2,1 stays in-group)
            acc += __shfl_xor_sync(0xffffffffu, acc, 4);
            acc += __shfl_xor_sync(0xffffffffu, acc, 2);
            acc += __shfl_xor_sync(0xffffffffu, acc, 1);

            if (s == 0) s_dot[wid][k * 4 + g] = acc;
        }
        __syncwarp();

        float myDot = s_dot[wid][lane];
        float myCos = myDot * invp;

        // ---- Phase 2: thread-per-edge MLP, two passes of 16 outputs ----
        if (e < E) {
            float p = s_bp;

            #pragma unroll
            for (int half = 0; half < 2; half++) {
                float h2[16];
                #pragma unroll
                for (int i = 0; i < 16; i++) h2[i] = s_b2[half * 16 + i];

                #pragma unroll 2
                for (int j = 0; j < 64; j++) {
                    float4 c = s_l1[j];
                    float hj = fmaxf(fmaf(myCos, c.x, fmaf(myDot, c.y, c.z)), 0.f);
                    const float* col = &s_W2T[j][half * 16];
                    #pragma unroll
                    for (int i = 0; i < 16; i++)
                        h2[i] = fmaf(col[i], hj, h2[i]);
                }

                #pragma unroll
                for (int i = 0; i < 16; i++)
                    p = fmaf(s_Wp[half * 16 + i], fmaxf(h2[i], 0.f), p);
            }

            out[e] = p;
        }
        __syncwarp();
    }
}

// ---------------------------------------------------------------------------
// Launch
// ---------------------------------------------------------------------------
extern "C" void kernel_launch(void* const* d_in, const int* in_sizes, int n_in,
                              void* d_out, int out_size) {
    const int2*  edge = (const int2*)d_in[0];     // int32 [E,2]
    const float* emb  = (const float*)d_in[1];    // [N,256]
    const float* wv   = (const float*)d_in[2];    // [1,256]
    const float* W1   = (const float*)d_in[3];    // [64,2]
    const float* b1   = (const float*)d_in[4];    // [64]
    const float* W2   = (const float*)d_in[5];    // [32,64]
    const float* b2   = (const float*)d_in[6];    // [32]
    const float* Wp   = (const float*)d_in[7];    // [1,32]
    const float* bp   = (const float*)d_in[8];    // [1]
    float* out = (float*)d_out;

    int E      = in_sizes[0] / 2;
    int nNodes = in_sizes[1] / D;

    int preBlocks = (nNodes * 32 + TPB - 1) / TPB;
    prescale_kernel<<<preBlocks, TPB>>>(emb, wv, nNodes);

    int totalWarps = MAIN_BLOCKS * (TPB / 32);
    edge_kernel<<<MAIN_BLOCKS, TPB>>>(edge, W1, b1, W2, b2, Wp, bp,
                                      out, E, totalWarps);
}